// round 1
// baseline (speedup 1.0000x reference)
#include <cuda_runtime.h>
#include <cuda_bf16.h>
#include <cstdint>

#define BB 65536
#define XX 362
#define GS 19
#define TM 128
#define NT 256
#define CJ 80
#define H1V 100
#define H2V 400

// ---- scratch (device globals; no allocation) ----
__device__ float g_att[BB * 6];
__device__ int   g_idx[BB * 6];
__device__ float g_pred[BB * 6];
__device__ int   g_list[3][BB];
__device__ int   g_count[3];

// Shared memory layout (floats) for k_mlp
//  sid:128  att:1024  w1:600  b1:100  b3:104  w4:832  b4:8  b2:80
//  h1:128*101=12928  w2:100*81=8100  w3:80*104=8320  h2:128*81=10368 (reused as redS 128*64)
#define SMEM_FLOATS (128 + 1024 + 600 + 100 + 104 + 832 + 8 + 80 + 12928 + 8100 + 8320 + 10368)
#define SMEM_BYTES  (SMEM_FLOATS * 4)

__global__ void k_reset() {
    if (threadIdx.x < 3) g_count[threadIdx.x] = 0;
}

// One warp per sample: argmax (first-occurrence), copy row to out, gather att, bucket by action.
__global__ void k_prep(const float* __restrict__ x, const int* __restrict__ act,
                       float* __restrict__ out) {
    int s = (blockIdx.x * blockDim.x + threadIdx.x) >> 5;
    int lane = threadIdx.x & 31;
    if (s >= BB) return;
    const float* row = x + (size_t)s * XX;
    float* orow = out + (size_t)s * XX;

    float best = -3.4e38f;
    int bidx = XX;
    for (int i = lane; i < XX; i += 32) {
        float v = row[i];
        orow[i] = v;
        if (v > best) { best = v; bidx = i; }   // strict > keeps first occurrence per lane
    }
#pragma unroll
    for (int off = 16; off; off >>= 1) {
        float ov = __shfl_down_sync(0xffffffffu, best, off);
        int oi = __shfl_down_sync(0xffffffffu, bidx, off);
        if (ov > best || (ov == best && oi < bidx)) { best = ov; bidx = oi; }
    }
    bidx = __shfl_sync(0xffffffffu, bidx, 0);

    if (lane < 6) {
        int id;
        if (lane == 0) id = 0;
        else if (lane == 1) id = bidx;          // pointer cell, unclamped
        else {
            int d = (lane == 2) ? -GS : (lane == 3) ? GS : (lane == 4) ? -1 : 1;
            id = bidx + d;
            id = id < 1 ? 1 : (id > XX - 1 ? XX - 1 : id);
        }
        g_idx[s * 6 + lane] = id;
        g_att[s * 6 + lane] = row[id];
    }
    if (lane == 0) {
        int a = act[s];
        int pos = atomicAdd(&g_count[a], 1);
        g_list[a][pos] = s;
    }
}

// Fused 4-layer MLP over a tile of 128 same-action samples.
__global__ __launch_bounds__(NT)
void k_mlp(const float* __restrict__ W1, const float* __restrict__ b1,
           const float* __restrict__ W2, const float* __restrict__ b2,
           const float* __restrict__ W3, const float* __restrict__ b3,
           const float* __restrict__ W4, const float* __restrict__ b4) {
    extern __shared__ float sm[];
    int a = blockIdx.y;
    int count = g_count[a];
    int m0g = blockIdx.x * TM;
    if (m0g >= count) return;
    int M = min(TM, count - m0g);
    int tid = threadIdx.x;

    int*   sid  = (int*)sm;               // 128
    float* attS = sm + 128;               // 128*8
    float* w1S  = attS + 1024;            // 600
    float* b1S  = w1S + 600;              // 100
    float* b3S  = b1S + 100;              // 104 (zero pad)
    float* w4S  = b3S + 104;              // 104*8 (zero pad)
    float* b4S  = w4S + 832;              // 8
    float* b2S  = b4S + 8;                // 80
    float* h1S  = b2S + 80;               // 128*101
    float* w2S  = h1S + 12928;            // 100*81
    float* w3S  = w2S + 8100;             // 80*104
    float* h2S  = w3S + 8320;             // 128*81 (reused as redS)

    if (tid < TM) sid[tid] = (tid < M) ? g_list[a][m0g + tid] : 0;
    for (int p = tid; p < 600; p += NT) w1S[p] = W1[a * 600 + p];
    for (int p = tid; p < 100; p += NT) b1S[p] = b1[a * 100 + p];
    for (int p = tid; p < 104; p += NT) b3S[p] = (p < 100) ? b3[a * 100 + p] : 0.f;
    for (int p = tid; p < 832; p += NT) {
        int k = p >> 3, o = p & 7;
        w4S[p] = (k < 100 && o < 6) ? W4[(a * 100 + k) * 6 + o] : 0.f;
    }
    if (tid < 8) b4S[tid] = (tid < 6) ? b4[a * 6 + tid] : 0.f;
    __syncthreads();
    for (int p = tid; p < 1024; p += NT) {
        int m = p >> 3, q = p & 7;
        attS[p] = (m < M && q < 6) ? g_att[sid[m] * 6 + q] : 0.f;
    }
    __syncthreads();

    // layer1: h1[m][i] = relu(att @ W1 + b1)
    for (int p = tid; p < TM * H1V; p += NT) {
        int m = p / H1V, i = p % H1V;
        float v = b1S[i];
#pragma unroll
        for (int q = 0; q < 6; q++) v += attS[m * 8 + q] * w1S[q * 100 + i];
        h1S[m * 101 + i] = fmaxf(v, 0.f);
    }

    int jg = tid & 7, mg = tid >> 3;
    int mB = mg * 4;
    int jB = jg * 10;
    int kB = jg * 13;

    float f3[4][13];
#pragma unroll
    for (int mi = 0; mi < 4; mi++)
#pragma unroll
        for (int ki = 0; ki < 13; ki++) f3[mi][ki] = 0.f;

    for (int jb = 0; jb < H2V; jb += CJ) {
        __syncthreads();  // protect weight/h2 tiles from previous iteration readers (and h1 writes first time)
        for (int p = tid; p < 100 * CJ; p += NT) {
            int i = p / CJ, j = p % CJ;
            w2S[i * 81 + j] = W2[(a * 100 + i) * 400 + jb + j];
        }
        for (int p = tid; p < CJ * 104; p += NT) {
            int j = p / 104, k = p % 104;
            w3S[j * 104 + k] = (k < 100) ? W3[(a * 400 + jb + j) * 100 + k] : 0.f;
        }
        if (tid < CJ) b2S[tid] = b2[a * 400 + jb + tid];
        __syncthreads();

        // layer2 chunk: h2[m][jb+j] = relu(h1 @ W2 + b2), micro-tile 4x10
        float acc[4][10];
#pragma unroll
        for (int mi = 0; mi < 4; mi++)
#pragma unroll
            for (int ji = 0; ji < 10; ji++) acc[mi][ji] = b2S[jB + ji];
#pragma unroll 2
        for (int i = 0; i < H1V; i++) {
            float av[4], wv[10];
#pragma unroll
            for (int mi = 0; mi < 4; mi++) av[mi] = h1S[(mB + mi) * 101 + i];
#pragma unroll
            for (int ji = 0; ji < 10; ji++) wv[ji] = w2S[i * 81 + jB + ji];
#pragma unroll
            for (int mi = 0; mi < 4; mi++)
#pragma unroll
                for (int ji = 0; ji < 10; ji++) acc[mi][ji] += av[mi] * wv[ji];
        }
#pragma unroll
        for (int mi = 0; mi < 4; mi++)
#pragma unroll
            for (int ji = 0; ji < 10; ji++)
                h2S[(mB + mi) * 81 + jB + ji] = fmaxf(acc[mi][ji], 0.f);
        __syncthreads();

        // layer3 accumulate into register-resident h3, micro-tile 4x13
#pragma unroll 2
        for (int j = 0; j < CJ; j++) {
            float hv[4], wv[13];
#pragma unroll
            for (int mi = 0; mi < 4; mi++) hv[mi] = h2S[(mB + mi) * 81 + j];
#pragma unroll
            for (int ki = 0; ki < 13; ki++) wv[ki] = w3S[j * 104 + kB + ki];
#pragma unroll
            for (int mi = 0; mi < 4; mi++)
#pragma unroll
                for (int ki = 0; ki < 13; ki++) f3[mi][ki] += hv[mi] * wv[ki];
        }
    }
    __syncthreads();  // before reusing h2S region as reduction buffer

    float* redS = h2S;  // [128][8][8]
#pragma unroll
    for (int mi = 0; mi < 4; mi++) {
        float po[6];
#pragma unroll
        for (int o = 0; o < 6; o++) po[o] = 0.f;
#pragma unroll
        for (int ki = 0; ki < 13; ki++) {
            int k = kB + ki;                         // pads (k>=100): f3=0, b3S=0, w4S=0
            float h3v = fmaxf(f3[mi][ki] + b3S[k], 0.f);
#pragma unroll
            for (int o = 0; o < 6; o++) po[o] += h3v * w4S[k * 8 + o];
        }
#pragma unroll
        for (int o = 0; o < 6; o++) redS[(mB + mi) * 64 + jg * 8 + o] = po[o];
    }
    __syncthreads();

    // deterministic tree-style reduction over the 8 k-groups, + b4
    for (int p = tid; p < TM * 6; p += NT) {
        int m = p / 6, o = p % 6;
        float sacc = b4S[o];
#pragma unroll
        for (int kg = 0; kg < 8; kg++) sacc += redS[m * 64 + kg * 8 + o];
        if (m < M) g_pred[sid[m] * 6 + o] = sacc;
    }
}

// out[s][idx_j] = x[s][idx_j] + pred[j], j ascending -> last index wins (set semantics)
__global__ void k_scatter(const float* __restrict__ x, float* __restrict__ out) {
    int s = blockIdx.x * blockDim.x + threadIdx.x;
    if (s >= BB) return;
    size_t base = (size_t)s * XX;
#pragma unroll
    for (int j = 0; j < 6; j++) {
        int id = g_idx[s * 6 + j];
        out[base + id] = x[base + id] + g_pred[s * 6 + j];
    }
}

extern "C" void kernel_launch(void* const* d_in, const int* in_sizes, int n_in,
                              void* d_out, int out_size) {
    const float* x  = (const float*)d_in[0];
    const float* W1 = (const float*)d_in[1];
    const float* b1 = (const float*)d_in[2];
    const float* W2 = (const float*)d_in[3];
    const float* b2 = (const float*)d_in[4];
    const float* W3 = (const float*)d_in[5];
    const float* b3 = (const float*)d_in[6];
    const float* W4 = (const float*)d_in[7];
    const float* b4 = (const float*)d_in[8];
    const int*  act = (const int*)d_in[9];
    float* out = (float*)d_out;

    cudaFuncSetAttribute(k_mlp, cudaFuncAttributeMaxDynamicSharedMemorySize, SMEM_BYTES);

    k_reset<<<1, 32>>>();
    k_prep<<<BB / 8, 256>>>(x, act, out);
    dim3 g2((BB + TM - 1) / TM, 3);
    k_mlp<<<g2, NT, SMEM_BYTES>>>(W1, b1, W2, b2, W3, b3, W4, b4);
    k_scatter<<<BB / 256, 256>>>(x, out);
}

// round 3
// speedup vs baseline: 1.6484x; 1.6484x over previous
#include <cuda_runtime.h>
#include <cuda_bf16.h>
#include <cstdint>

#define BB 65536
#define XX 362
#define GS 19
#define TM 128

// ---- weight image (per action,chunk): B2 [128n][120k] hi/lo, B3 [112n][136k] hi/lo ----
#define IMG_B2 0
#define IMG_B2_BYTES 61440
#define IMG_B3 61440
#define IMG_B3_BYTES 60928
#define IMGSZ 122368

// ---- smem layout (bytes) ----
#define OFF_WBUF 0
#define OFF_H1   61440
#define OFF_H2   122880
#define OFF_ATT  192512
#define OFF_W1   196608
#define OFF_B1   199008
#define OFF_B2   199408
#define OFF_B3   201456
#define OFF_W4   201904
#define OFF_B4   205488
#define OFF_SID  205520
#define SMEM_BYTES 206080

// ---- device scratch ----
__device__ float g_att[BB * 6];
__device__ int   g_idx[BB * 6];
__device__ float g_pred[BB * 6];
__device__ int   g_list[3][BB];
__device__ int   g_count[3];
__device__ __align__(16) unsigned char g_wimg[12 * IMGSZ];

__device__ __forceinline__ uint32_t pack2(float e, float o) {
    __nv_bfloat162 t = __floats2bfloat162_rn(e, o);
    return *reinterpret_cast<uint32_t*>(&t);
}
__device__ __forceinline__ void mma16816(float* c, const uint32_t* a, uint32_t b0, uint32_t b1) {
    asm volatile("mma.sync.aligned.m16n8k16.row.col.f32.bf16.bf16.f32 "
                 "{%0,%1,%2,%3}, {%4,%5,%6,%7}, {%8,%9}, {%0,%1,%2,%3};"
                 : "+f"(c[0]), "+f"(c[1]), "+f"(c[2]), "+f"(c[3])
                 : "r"(a[0]), "r"(a[1]), "r"(a[2]), "r"(a[3]), "r"(b0), "r"(b1));
}

// ================= small kernels =================
__global__ void k_reset() {
    if (threadIdx.x < 3) g_count[threadIdx.x] = 0;
}

// Pre-convert W2^T / W3^T to bf16 hi/lo padded [N][K] images.
__global__ void k_prepw(const float* __restrict__ W2, const float* __restrict__ W3) {
    int img = blockIdx.x;           // a*4 + c
    int a = img >> 2, c = img & 3;
    unsigned char* base = g_wimg + (size_t)img * IMGSZ;
    __nv_bfloat16* b2h = (__nv_bfloat16*)(base + IMG_B2);
    __nv_bfloat16* b2l = b2h + 15360;
    __nv_bfloat16* b3h = (__nv_bfloat16*)(base + IMG_B3);
    __nv_bfloat16* b3l = b3h + 15232;
    for (int p = threadIdx.x; p < 128 * 120; p += blockDim.x) {
        int n = p / 120, k = p % 120;
        int gn = c * 128 + n;
        float v = (k < 100 && gn < 400) ? W2[(a * 100 + k) * 400 + gn] : 0.f;
        __nv_bfloat16 h = __float2bfloat16(v);
        b2h[p] = h;
        b2l[p] = __float2bfloat16(v - __bfloat162float(h));
    }
    for (int p = threadIdx.x; p < 112 * 136; p += blockDim.x) {
        int n = p / 136, k = p % 136;
        int gk = c * 128 + k;
        float v = (n < 100 && k < 128 && gk < 400) ? W3[(a * 400 + gk) * 100 + n] : 0.f;
        __nv_bfloat16 h = __float2bfloat16(v);
        b3h[p] = h;
        b3l[p] = __float2bfloat16(v - __bfloat162float(h));
    }
}

// One warp per sample: argmax, row copy, gather att, bucket by action.
__global__ void k_prep(const float* __restrict__ x, const int* __restrict__ act,
                       float* __restrict__ out) {
    int s = (blockIdx.x * blockDim.x + threadIdx.x) >> 5;
    int lane = threadIdx.x & 31;
    if (s >= BB) return;
    const float* row = x + (size_t)s * XX;
    float* orow = out + (size_t)s * XX;

    float best = -3.4e38f;
    int bidx = XX;
    for (int i = lane; i < XX; i += 32) {
        float v = row[i];
        orow[i] = v;
        if (v > best) { best = v; bidx = i; }
    }
#pragma unroll
    for (int off = 16; off; off >>= 1) {
        float ov = __shfl_down_sync(0xffffffffu, best, off);
        int oi = __shfl_down_sync(0xffffffffu, bidx, off);
        if (ov > best || (ov == best && oi < bidx)) { best = ov; bidx = oi; }
    }
    bidx = __shfl_sync(0xffffffffu, bidx, 0);

    if (lane < 6) {
        int id;
        if (lane == 0) id = 0;
        else if (lane == 1) id = bidx;
        else {
            int d = (lane == 2) ? -GS : (lane == 3) ? GS : (lane == 4) ? -1 : 1;
            id = bidx + d;
            id = id < 1 ? 1 : (id > XX - 1 ? XX - 1 : id);
        }
        g_idx[s * 6 + lane] = id;
        g_att[s * 6 + lane] = row[id];
    }
    if (lane == 0) {
        int a = act[s];
        int pos = atomicAdd(&g_count[a], 1);
        g_list[a][pos] = s;
    }
}

// ================= mma.sync MLP =================
__global__ __launch_bounds__(256)
void k_mlp(const float* __restrict__ W1, const float* __restrict__ b1,
           const float* __restrict__ b2, const float* __restrict__ b3,
           const float* __restrict__ W4, const float* __restrict__ b4) {
    extern __shared__ char sm[];
    int a = blockIdx.y;
    int count = g_count[a];
    int m0 = blockIdx.x * TM;
    if (m0 >= count) return;
    int M = min(TM, count - m0);
    int tid = threadIdx.x;
    int wid = tid >> 5, lane = tid & 31;
    int grp = lane >> 2, qid = lane & 3;
    int wm = wid >> 1, wn = wid & 1;

    int*   sid  = (int*)(sm + OFF_SID);
    float* attS = (float*)(sm + OFF_ATT);
    float* w1S  = (float*)(sm + OFF_W1);
    float* b1S  = (float*)(sm + OFF_B1);
    float* b2S  = (float*)(sm + OFF_B2);
    float* b3S  = (float*)(sm + OFF_B3);
    float* w4S  = (float*)(sm + OFF_W4);
    float* b4S  = (float*)(sm + OFF_B4);

    uint32_t* wbH = (uint32_t*)(sm + OFF_WBUF);      // B2: stride 60 words; B3: stride 68
    uint32_t* h1H = (uint32_t*)(sm + OFF_H1);        // [128][60w] bf16x2
    uint32_t* h1L = h1H + 7680;
    uint32_t* h2H = (uint32_t*)(sm + OFF_H2);        // [128][68w]
    uint32_t* h2L = h2H + 8704;

    // ---- stage misc ----
    if (tid < TM) sid[tid] = (tid < M) ? g_list[a][m0 + tid] : 0;
    for (int p = tid; p < 600; p += 256) w1S[p] = W1[a * 600 + p];
    for (int p = tid; p < 100; p += 256) b1S[p] = b1[a * 100 + p];
    for (int p = tid; p < 512; p += 256) b2S[p] = (p < 400) ? b2[a * 400 + p] : 0.f;
    for (int p = tid; p < 112; p += 256) b3S[p] = (p < 100) ? b3[a * 100 + p] : 0.f;
    for (int p = tid; p < 896; p += 256) {
        int k = p >> 3, o = p & 7;
        w4S[p] = (k < 100 && o < 6) ? W4[(a * 100 + k) * 6 + o] : 0.f;
    }
    if (tid < 8) b4S[tid] = (tid < 6) ? b4[a * 6 + tid] : 0.f;
    __syncthreads();
    for (int p = tid; p < 1024; p += 256) {
        int m = p >> 3, q = p & 7;
        attS[p] = (m < M && q < 6) ? g_att[sid[m] * 6 + q] : 0.f;
    }
    __syncthreads();

    // ---- layer1 (scalar): h1 = relu(att@W1+b1), bf16 hi/lo, [128][120] cols 0..111 valid ----
    {
        int m = tid >> 1;
        int i0 = (tid & 1) * 56;
        float at[6];
#pragma unroll
        for (int q = 0; q < 6; q++) at[q] = attS[m * 8 + q];
        __nv_bfloat16* hh = (__nv_bfloat16*)h1H;
        __nv_bfloat16* hl = (__nv_bfloat16*)h1L;
#pragma unroll 4
        for (int ii = 0; ii < 56; ii++) {
            int i = i0 + ii;
            float v = 0.f;
            if (i < 100) {
                v = b1S[i];
#pragma unroll
                for (int q = 0; q < 6; q++) v += at[q] * w1S[q * 100 + i];
                v = fmaxf(v, 0.f);
            }
            __nv_bfloat16 h = __float2bfloat16(v);
            hh[m * 120 + i] = h;
            hl[m * 120 + i] = __float2bfloat16(v - __bfloat162float(h));
        }
    }

    const unsigned char* img = g_wimg + (size_t)(a * 4) * IMGSZ;
    float acc3[2][7][4];
#pragma unroll
    for (int mt = 0; mt < 2; mt++)
#pragma unroll
        for (int nt = 0; nt < 7; nt++)
#pragma unroll
            for (int e = 0; e < 4; e++) acc3[mt][nt][e] = 0.f;

    for (int c = 0; c < 4; c++) {
        __syncthreads();   // h1 ready (c=0) / prev chunk readers done
        {   // stage W2 chunk (hi+lo contiguous)
            const uint4* src = (const uint4*)(img + (size_t)c * IMGSZ + IMG_B2);
            uint4* dst = (uint4*)(sm + OFF_WBUF);
            for (int p = tid; p < IMG_B2_BYTES / 16; p += 256) dst[p] = src[p];
        }
        __syncthreads();

        // ---- layer2 chunk: C[128x128] = h1 @ W2c ----
        float acc2[2][8][4];
#pragma unroll
        for (int mt = 0; mt < 2; mt++)
#pragma unroll
            for (int nt = 0; nt < 8; nt++)
#pragma unroll
                for (int e = 0; e < 4; e++) acc2[mt][nt][e] = 0.f;

        uint32_t* w2L = wbH + 7680;
#pragma unroll
        for (int pass = 0; pass < 3; pass++) {
            const uint32_t* Aw = (pass == 2) ? h1L : h1H;
            const uint32_t* Bw = (pass == 1) ? w2L : wbH;
#pragma unroll
            for (int kk = 0; kk < 7; kk++) {
                uint32_t af[2][4];
#pragma unroll
                for (int mt = 0; mt < 2; mt++) {
                    int r = wm * 32 + mt * 16 + grp;
                    af[mt][0] = Aw[r * 60 + kk * 8 + qid];
                    af[mt][1] = Aw[(r + 8) * 60 + kk * 8 + qid];
                    af[mt][2] = Aw[r * 60 + kk * 8 + 4 + qid];
                    af[mt][3] = Aw[(r + 8) * 60 + kk * 8 + 4 + qid];
                }
#pragma unroll
                for (int nt = 0; nt < 8; nt++) {
                    int n = wn * 64 + nt * 8 + grp;
                    uint32_t b0 = Bw[n * 60 + kk * 8 + qid];
                    uint32_t bq = Bw[n * 60 + kk * 8 + 4 + qid];
                    mma16816(acc2[0][nt], af[0], b0, bq);
                    mma16816(acc2[1][nt], af[1], b0, bq);
                }
            }
        }
        // epilogue: h2 = relu(C + b2), bf16 hi/lo
#pragma unroll
        for (int mt = 0; mt < 2; mt++) {
            int r = wm * 32 + mt * 16 + grp;
#pragma unroll
            for (int nt = 0; nt < 8; nt++) {
                int cn = wn * 64 + nt * 8 + qid * 2;
                float bb0 = b2S[c * 128 + cn], bb1 = b2S[c * 128 + cn + 1];
                float v00 = fmaxf(acc2[mt][nt][0] + bb0, 0.f);
                float v01 = fmaxf(acc2[mt][nt][1] + bb1, 0.f);
                float v10 = fmaxf(acc2[mt][nt][2] + bb0, 0.f);
                float v11 = fmaxf(acc2[mt][nt][3] + bb1, 0.f);
                float h00 = __bfloat162float(__float2bfloat16(v00));
                float h01 = __bfloat162float(__float2bfloat16(v01));
                float h10 = __bfloat162float(__float2bfloat16(v10));
                float h11 = __bfloat162float(__float2bfloat16(v11));
                h2H[r * 68 + cn / 2]       = pack2(h00, h01);
                h2L[r * 68 + cn / 2]       = pack2(v00 - h00, v01 - h01);
                h2H[(r + 8) * 68 + cn / 2] = pack2(h10, h11);
                h2L[(r + 8) * 68 + cn / 2] = pack2(v10 - h10, v11 - h11);
            }
        }
        __syncthreads();   // all h2 written, W buffer reads done
        {   // stage W3 chunk
            const uint4* src = (const uint4*)(img + (size_t)c * IMGSZ + IMG_B3);
            uint4* dst = (uint4*)(sm + OFF_WBUF);
            for (int p = tid; p < IMG_B3_BYTES / 16; p += 256) dst[p] = src[p];
        }
        __syncthreads();

        // ---- layer3 partial: acc3 += h2c @ W3c ----
        uint32_t* w3L = wbH + 7616;
#pragma unroll
        for (int pass = 0; pass < 3; pass++) {
            const uint32_t* Aw = (pass == 2) ? h2L : h2H;
            const uint32_t* Bw = (pass == 1) ? w3L : wbH;
#pragma unroll
            for (int kk = 0; kk < 8; kk++) {
                uint32_t af[2][4];
#pragma unroll
                for (int mt = 0; mt < 2; mt++) {
                    int r = wm * 32 + mt * 16 + grp;
                    af[mt][0] = Aw[r * 68 + kk * 8 + qid];
                    af[mt][1] = Aw[(r + 8) * 68 + kk * 8 + qid];
                    af[mt][2] = Aw[r * 68 + kk * 8 + 4 + qid];
                    af[mt][3] = Aw[(r + 8) * 68 + kk * 8 + 4 + qid];
                }
#pragma unroll
                for (int nt = 0; nt < 7; nt++) {
                    int n = wn * 56 + nt * 8 + grp;
                    uint32_t b0 = Bw[n * 68 + kk * 8 + qid];
                    uint32_t bq = Bw[n * 68 + kk * 8 + 4 + qid];
                    mma16816(acc3[0][nt], af[0], b0, bq);
                    mma16816(acc3[1][nt], af[1], b0, bq);
                }
            }
        }
    }
    __syncthreads();   // everyone done with h1 region reads (layer2 long past); reuse as h3

    // ---- epilogue3: h3 = relu(acc3 + b3) -> fp32 smem [128][113] ----
    float* h3S = (float*)(sm + OFF_H1);
#pragma unroll
    for (int mt = 0; mt < 2; mt++) {
        int r = wm * 32 + mt * 16 + grp;
#pragma unroll
        for (int nt = 0; nt < 7; nt++) {
            int cn = wn * 56 + nt * 8 + qid * 2;
            float bb0 = b3S[cn], bb1 = b3S[cn + 1];
            h3S[r * 113 + cn]           = fmaxf(acc3[mt][nt][0] + bb0, 0.f);
            h3S[r * 113 + cn + 1]       = fmaxf(acc3[mt][nt][1] + bb1, 0.f);
            h3S[(r + 8) * 113 + cn]     = fmaxf(acc3[mt][nt][2] + bb0, 0.f);
            h3S[(r + 8) * 113 + cn + 1] = fmaxf(acc3[mt][nt][3] + bb1, 0.f);
        }
    }
    __syncthreads();

    // ---- layer4 (scalar): pred = h3 @ W4 + b4 ----
    {
        int m = tid >> 1;
        int os = (tid & 1) * 3;
        float pr[3] = {b4S[os], b4S[os + 1], b4S[os + 2]};
#pragma unroll 4
        for (int k = 0; k < 112; k++) {
            float h = h3S[m * 113 + k];
#pragma unroll
            for (int j = 0; j < 3; j++) pr[j] += h * w4S[k * 8 + os + j];
        }
        if (m < M) {
            int s = sid[m];
#pragma unroll
            for (int j = 0; j < 3; j++) g_pred[s * 6 + os + j] = pr[j];
        }
    }
}

__global__ void k_scatter(const float* __restrict__ x, float* __restrict__ out) {
    int s = blockIdx.x * blockDim.x + threadIdx.x;
    if (s >= BB) return;
    size_t base = (size_t)s * XX;
#pragma unroll
    for (int j = 0; j < 6; j++) {
        int id = g_idx[s * 6 + j];
        out[base + id] = x[base + id] + g_pred[s * 6 + j];
    }
}

extern "C" void kernel_launch(void* const* d_in, const int* in_sizes, int n_in,
                              void* d_out, int out_size) {
    const float* x  = (const float*)d_in[0];
    const float* W1 = (const float*)d_in[1];
    const float* b1 = (const float*)d_in[2];
    const float* W2 = (const float*)d_in[3];
    const float* b2 = (const float*)d_in[4];
    const float* W3 = (const float*)d_in[5];
    const float* b3 = (const float*)d_in[6];
    const float* W4 = (const float*)d_in[7];
    const float* b4 = (const float*)d_in[8];
    const int*  act = (const int*)d_in[9];
    float* out = (float*)d_out;

    cudaFuncSetAttribute(k_mlp, cudaFuncAttributeMaxDynamicSharedMemorySize, SMEM_BYTES);

    k_reset<<<1, 32>>>();
    k_prepw<<<12, 256>>>(W2, W3);
    k_prep<<<BB / 8, 256>>>(x, act, out);
    dim3 g2((BB + TM - 1) / TM, 3);
    k_mlp<<<g2, 256, SMEM_BYTES>>>(W1, b1, b2, b3, W4, b4);
    k_scatter<<<BB / 256, 256>>>(x, out);
}